// round 9
// baseline (speedup 1.0000x reference)
#include <cuda_runtime.h>
#include <cstdint>

#define IMG_N 128
#define B_N 64
#define PIX 262144
#define CAP 2048
#define NSAMP 1000
#define NPAIR 500
// valid ord = 0x800000 + k, k in [0, 2^22]. k0 = 2^22 - 24576 => E[cand] ~ 1500.
#define K0_ORD 0xBFA000u
#define SENTF 16384.0f
#define SENTQ 536870912.0f

// ---------------- static scratch (no allocations allowed) ----------------
__device__ uint2 g_imgkeys[IMG_N];
__device__ unsigned long long g_cand[IMG_N * CAP];
__device__ unsigned int g_candCnt[IMG_N];
__device__ unsigned int g_validCnt[IMG_N];
// t-side layout: per pair of points {x0,x1,y0,y1} + {q0,q1}; p-side: {x,y,pp2,valid}
__device__ float4 g_txy[IMG_N * NPAIR];
__device__ float2 g_tq[IMG_N * NPAIR];
__device__ float4 g_pp[IMG_N * NSAMP];
__device__ float g_a2[B_N * 2];

// ---------------- packed f32x2 helpers ----------------
__device__ __forceinline__ unsigned long long fma2(unsigned long long a,
                                                   unsigned long long b,
                                                   unsigned long long c) {
    unsigned long long d;
    asm("fma.rn.f32x2 %0, %1, %2, %3;" : "=l"(d) : "l"(a), "l"(b), "l"(c));
    return d;
}
__device__ __forceinline__ unsigned long long pack2(float a, float b) {
    unsigned long long d;
    asm("mov.b64 %0, {%1, %2};" : "=l"(d) : "f"(a), "f"(b));
    return d;
}
__device__ __forceinline__ void unpack2(unsigned long long v, float& a, float& b) {
    asm("mov.b64 {%0, %1}, %2;" : "=f"(a), "=f"(b) : "l"(v));
}

// ---------------- threefry2x32 (partitionable JAX semantics) ----------------
__device__ __forceinline__ uint2 threefry(unsigned k0, unsigned k1,
                                          unsigned x0, unsigned x1) {
    unsigned ks2 = k0 ^ k1 ^ 0x1BD11BDAu;
    x0 += k0; x1 += k1;
#define TF_RND(r) { x0 += x1; x1 = __funnelshift_l(x1, x1, (r)); x1 ^= x0; }
    TF_RND(13) TF_RND(15) TF_RND(26) TF_RND(6)   x0 += k1;  x1 += ks2 + 1u;
    TF_RND(17) TF_RND(29) TF_RND(16) TF_RND(24)  x0 += ks2; x1 += k0 + 2u;
    TF_RND(13) TF_RND(15) TF_RND(26) TF_RND(6)   x0 += k0;  x1 += k1 + 3u;
    TF_RND(17) TF_RND(29) TF_RND(16) TF_RND(24)  x0 += k1;  x1 += ks2 + 4u;
    TF_RND(13) TF_RND(15) TF_RND(26) TF_RND(6)   x0 += ks2; x1 += k0 + 5u;
#undef TF_RND
    return make_uint2(x0, x1);
}
__device__ __forceinline__ unsigned tfBits32(unsigned k0, unsigned k1, unsigned j) {
    uint2 r = threefry(k0, k1, 0u, j);
    return r.x ^ r.y;
}
// Order key for a VALID pixel: monotone in score = RNE(2.0f + u), u = (bits>>9)*2^-23.
__device__ __forceinline__ unsigned makeOrdValid(unsigned bits) {
    unsigned m = bits >> 9;
    float u = __uint_as_float(0x3F800000u | m) - 1.0f;  // exact
    float s = 2.0f + u;                                  // hardware RNE == XLA add
    return 0x800000u + (__float_as_uint(s) - 0x40000000u);
}

// fast sigmoid (used consistently in hot path AND fallback revalidation)
__device__ __forceinline__ float fsig(float v) {
    return __fdividef(1.0f, 1.0f + __expf(-v));
}

// emit point into both t-side (packed) and p-side layouts
__device__ __forceinline__ void emitPoint(int img, int s, float x, float y,
                                          float q, float valid) {
    int pi = s >> 1, h = s & 1;
    float* a = (float*)&g_txy[img * NPAIR + pi];
    a[h] = x; a[2 + h] = y;
    ((float*)&g_tq[img * NPAIR + pi])[h] = q;
    g_pp[img * NSAMP + s] = make_float4(x, y, q, valid);
}

// recompute validity of pixel j in image img from raw inputs (fallback only)
__device__ bool validAt(int img, unsigned j, const float* pred, const float* tgt) {
    const float* src = (img < 64) ? (pred + (size_t)img * PIX)
                                  : (tgt + (size_t)(img - 64) * PIX);
    bool isPred = img < 64;
    int y = (int)(j >> 9), x = (int)(j & 511u);
    float a[3][3];
#pragma unroll
    for (int dy = -1; dy <= 1; dy++)
#pragma unroll
        for (int dx = -1; dx <= 1; dx++) {
            int gy = y + dy, gx = x + dx;
            float v = 0.0f;
            if (gy >= 0 && gy < 512 && gx >= 0 && gx < 512) {
                v = __ldg(src + (size_t)gy * 512 + gx);
                if (isPred) v = fsig(v);
            }
            a[dy + 1][dx + 1] = v;
        }
    float gxv = (a[0][2] - a[0][0]) + 2.0f * (a[1][2] - a[1][0]) + (a[2][2] - a[2][0]);
    float gyv = (a[2][0] - a[0][0]) + 2.0f * (a[2][1] - a[0][1]) + (a[2][2] - a[0][2]);
    float v2 = gxv * gxv + gyv * gyv + 1e-8f;
    return __fsqrt_rn(v2) > 0.1f;
}

// ---------------- kernels ----------------
// init: zero counters + foldlike split keys = split(key(1),128): key_j = TF(0,1,0,j)
__global__ void kernInit() {
    unsigned j = threadIdx.x;
    if (j < IMG_N) {
        g_candCnt[j] = 0u;
        g_validCnt[j] = 0u;
        g_imgkeys[j] = threefry(0u, 1u, 0u, j);
    }
}

// FUSED: sigmoid/identity -> Sobel -> valid -> threefry -> candidate collection.
__global__ __launch_bounds__(1024) void kernValidCand(const float* __restrict__ pred,
                                                      const float* __restrict__ tgt) {
    __shared__ float s[34][36];
    int img = blockIdx.z;
    int bx = blockIdx.x * 32, by = blockIdx.y * 32;
    int tx = threadIdx.x, ty = threadIdx.y;
    int tid = ty * 32 + tx;
    const float* src = (img < 64) ? (pred + (size_t)img * PIX)
                                  : (tgt + (size_t)(img - 64) * PIX);
    bool isPred = img < 64;
    for (int i = tid; i < 34 * 34; i += 1024) {
        int hy = i / 34, hx = i % 34;
        int gy = by + hy - 1, gx = bx + hx - 1;
        float v = 0.0f;
        if (gy >= 0 && gy < 512 && gx >= 0 && gx < 512) {
            v = __ldg(src + (size_t)gy * 512 + gx);
            if (isPred) v = fsig(v);
        }
        s[hy][hx] = v;
    }
    __syncthreads();
    int hy = ty + 1, hx = tx + 1;
    float a00 = s[hy - 1][hx - 1], a01 = s[hy - 1][hx], a02 = s[hy - 1][hx + 1];
    float a10 = s[hy][hx - 1],                          a12 = s[hy][hx + 1];
    float a20 = s[hy + 1][hx - 1], a21 = s[hy + 1][hx], a22 = s[hy + 1][hx + 1];
    float gxv = (a02 - a00) + 2.0f * (a12 - a10) + (a22 - a20);
    float gyv = (a20 - a00) + 2.0f * (a21 - a01) + (a22 - a02);
    float v2 = gxv * gxv + gyv * gyv + 1e-8f;
    int valid = (__fsqrt_rn(v2) > 0.1f) ? 1 : 0;
    unsigned j = (unsigned)(by + ty) * 512u + (unsigned)(bx + tx);

    // per-warp valid count straight to L2 (spread over 128 addresses; hidden)
    unsigned bal = __ballot_sync(0xFFFFFFFFu, valid);
    if ((tid & 31) == 0) atomicAdd(&g_validCnt[img], (unsigned)__popc(bal));

    if (valid) {
        uint2 kk = g_imgkeys[img];
        unsigned ord = makeOrdValid(tfBits32(kk.x, kk.y, j));
        if (ord >= K0_ORD) {
            unsigned pos = atomicAdd(&g_candCnt[img], 1u);
            if (pos < CAP)
                g_cand[(size_t)img * CAP + pos] =
                    ((unsigned long long)ord << 18) | (unsigned long long)(j ^ 0x3FFFFu);
        }
    }
}

// per-image bitonic sort of <=2048 candidates (descending), emit top 1000 points
__global__ __launch_bounds__(1024) void kernSort() {
    __shared__ unsigned long long s[CAP];
    int img = blockIdx.x;
    unsigned cnt = g_candCnt[img];
    unsigned n = cnt > CAP ? CAP : cnt;
    for (int i = threadIdx.x; i < CAP; i += 1024)
        s[i] = (i < (int)n) ? g_cand[(size_t)img * CAP + i] : 0ull;
    __syncthreads();
    for (int k = 2; k <= CAP; k <<= 1) {
        for (int jj = k >> 1; jj > 0; jj >>= 1) {
            for (int i = threadIdx.x; i < CAP; i += 1024) {
                int ixj = i ^ jj;
                if (ixj > i) {
                    unsigned long long a = s[i], b = s[ixj];
                    bool desc = (i & k) == 0;
                    if (desc ? (a < b) : (a > b)) { s[i] = b; s[ixj] = a; }
                }
            }
            __syncthreads();
        }
    }
    if (threadIdx.x < NSAMP) {
        unsigned long long p = s[threadIdx.x];
        unsigned idx = ((unsigned)p & 0x3FFFFu) ^ 0x3FFFFu;
        float x = (float)(idx >> 9), y = (float)(idx & 511u);
        emitPoint(img, threadIdx.x, x, y, x * x + y * y, 1.0f);
    }
}

// exact fallback for degenerate images (never triggers on healthy inputs)
__global__ __launch_bounds__(256) void kernFallback(const float* __restrict__ pred,
                                                    const float* __restrict__ tgt) {
    int img = blockIdx.x;
    unsigned V = g_validCnt[img];
    unsigned cnt = g_candCnt[img];
    bool need = (V < NSAMP) || (cnt < NSAMP) || (cnt > CAP);
    if (!need) return;
    int tid = threadIdx.x;

    if (V == 0) {  // has_any == False: single center point
        for (int i = tid; i < NSAMP; i += 256) {
            if (i == 0) emitPoint(img, 0, 256.0f, 256.0f, 131072.0f, 1.0f);
            else emitPoint(img, i, SENTF, SENTF, SENTQ, 0.0f);
        }
        return;
    }
    if (V < NSAMP) {  // take ALL valid points; rest masked sentinels
        __shared__ unsigned c2;
        if (tid == 0) c2 = 0;
        __syncthreads();
        for (unsigned p = tid; p < PIX; p += 256) {
            if (validAt(img, p, pred, tgt)) {
                unsigned pos = atomicAdd(&c2, 1u);
                float x = (float)(p >> 9), y = (float)(p & 511u);
                emitPoint(img, pos, x, y, x * x + y * y, 1.0f);
            }
        }
        __syncthreads();
        for (unsigned i = V + tid; i < NSAMP; i += 256)
            emitPoint(img, i, SENTF, SENTF, SENTQ, 0.0f);
        return;
    }
    // V >= NSAMP but threshold capture failed: exact radix select over valid ords
    __shared__ unsigned hist[2048];
    __shared__ unsigned long long buf[2048];
    __shared__ unsigned bufCnt, outCnt, selB, selNeed;
    for (int i = tid; i < 2048; i += 256) hist[i] = 0;
    if (tid == 0) { bufCnt = 0; outCnt = 0; }
    __syncthreads();
    uint2 kk = g_imgkeys[img];
    for (unsigned j = tid; j < PIX; j += 256) {
        if (validAt(img, j, pred, tgt)) {
            unsigned k = makeOrdValid(tfBits32(kk.x, kk.y, j)) - 0x800000u;
            atomicAdd(&hist[min(k >> 11, 2047u)], 1u);
        }
    }
    __syncthreads();
    if (tid == 0) {
        unsigned acc = 0; int b = 2047;
        for (; b > 0; b--) {
            if (acc + hist[b] >= NSAMP) break;
            acc += hist[b];
        }
        selB = (unsigned)b;
        selNeed = NSAMP - acc;
    }
    __syncthreads();
    unsigned sb = selB;
    for (unsigned j = tid; j < PIX; j += 256) {
        if (!validAt(img, j, pred, tgt)) continue;
        unsigned k = makeOrdValid(tfBits32(kk.x, kk.y, j)) - 0x800000u;
        unsigned bk = min(k >> 11, 2047u);
        if (bk > sb) {
            unsigned pos = atomicAdd(&outCnt, 1u);
            float x = (float)(j >> 9), y = (float)(j & 511u);
            emitPoint(img, pos, x, y, x * x + y * y, 1.0f);
        } else if (bk == sb) {
            unsigned pos = atomicAdd(&bufCnt, 1u);
            if (pos < 2048u)
                buf[pos] = ((unsigned long long)k << 18) |
                           (unsigned long long)(j ^ 0x3FFFFu);
        }
    }
    __syncthreads();
    unsigned bn = min(bufCnt, 2048u);
    for (int i = tid; i < 2048; i += 256)
        if (i >= (int)bn) buf[i] = 0ull;
    __syncthreads();
    for (int k2 = 2; k2 <= 2048; k2 <<= 1) {
        for (int jj = k2 >> 1; jj > 0; jj >>= 1) {
            for (int i = tid; i < 2048; i += 256) {
                int ixj = i ^ jj;
                if (ixj > i) {
                    unsigned long long a = buf[i], b = buf[ixj];
                    if (((i & k2) == 0) ? (a < b) : (a > b)) { buf[i] = b; buf[ixj] = a; }
                }
            }
            __syncthreads();
        }
    }
    unsigned baseOut = outCnt;
    for (unsigned i = tid; i < selNeed; i += 256) {
        unsigned long long p = buf[i];
        unsigned idx = ((unsigned)p & 0x3FFFFu) ^ 0x3FFFFu;
        float x = (float)(idx >> 9), y = (float)(idx & 511u);
        emitPoint(img, baseOut + i, x, y, x * x + y * y, 1.0f);
    }
}

// directed Hausdorff: min_t d2 = pp2 + min_t(qt - 2px*tx - 2py*ty).
// All real values are exact integers in fp32 (<2^24) -> bit-identical to reference d2.
// Packed f32x2 FFMA processes two t-points per instruction chain.
__global__ __launch_bounds__(1024) void kernHaus() {
    __shared__ float4 sxy[NPAIR];   // {x0,x1,y0,y1} per pair
    __shared__ float2 sq[NPAIR];    // {q0,q1}
    __shared__ float wmax[32];
    int b = blockIdx.x;
    int dir = blockIdx.y;
    int pimg = dir == 0 ? b : 64 + b;
    int timg = dir == 0 ? 64 + b : b;
    int tid = threadIdx.x;
    if (tid < NPAIR) {
        sxy[tid] = g_txy[timg * NPAIR + tid];
        sq[tid] = g_tq[timg * NPAIR + tid];
    }
    __syncthreads();
    float best = -1.0f;
    if (tid < NSAMP) {
        float4 p = g_pp[pimg * NSAMP + tid];
        unsigned long long m2x2 = pack2(-2.0f * p.x, -2.0f * p.x);
        unsigned long long m2y2 = pack2(-2.0f * p.y, -2.0f * p.y);
        const ulonglong2* sxyP = reinterpret_cast<const ulonglong2*>(sxy);
        const unsigned long long* sqP = reinterpret_cast<const unsigned long long*>(sq);
        float m0 = 3.4e38f, m1 = 3.4e38f, m2 = 3.4e38f, m3 = 3.4e38f;
#pragma unroll 2
        for (int i = 0; i < NPAIR; i += 2) {
            ulonglong2 xyA = sxyP[i];
            ulonglong2 xyB = sxyP[i + 1];
            unsigned long long vA = fma2(xyA.x, m2x2, fma2(xyA.y, m2y2, sqP[i]));
            unsigned long long vB = fma2(xyB.x, m2x2, fma2(xyB.y, m2y2, sqP[i + 1]));
            float a0, a1, b0, b1;
            unpack2(vA, a0, a1);
            unpack2(vB, b0, b1);
            m0 = fminf(m0, a0); m1 = fminf(m1, a1);
            m2 = fminf(m2, b0); m3 = fminf(m3, b1);
        }
        float vmin = fminf(fminf(m0, m1), fminf(m2, m3));
        float d2 = p.z + vmin;          // exact: pp2 + (d2 - pp2)
        best = (p.w > 0.0f) ? d2 : -1.0f;
    }
    for (int o = 16; o > 0; o >>= 1)
        best = fmaxf(best, __shfl_xor_sync(0xFFFFFFFFu, best, o));
    if ((tid & 31) == 0) wmax[tid >> 5] = best;
    __syncthreads();
    if (tid == 0) {
        float r = wmax[0];
        for (int w = 1; w < 32; w++) r = fmaxf(r, wmax[w]);
        g_a2[b * 2 + dir] = r;
    }
}

__global__ void kernFinal(float* __restrict__ out) {
    __shared__ float hd[64];
    int t = threadIdx.x;
    if (t < 64) {
        float a = __fsqrt_rn(g_a2[t * 2 + 0]);
        float c = __fsqrt_rn(g_a2[t * 2 + 1]);
        float m = fmaxf(a, c);
        float diag = __fsqrt_rn(524288.0f);
        float h = __fdiv_rn(m, diag);
        h = fminf(fmaxf(h, 0.0f), 0.1f);
        hd[t] = h;
    }
    __syncthreads();
    if (t == 0) {
        float s = 0.0f;
        for (int i = 0; i < 64; i++) s += hd[i];
        out[0] = s * (1.0f / 64.0f);
    }
}

extern "C" void kernel_launch(void* const* d_in, const int* in_sizes, int n_in,
                              void* d_out, int out_size) {
    const float* pred = (const float*)d_in[0];
    const float* tgt = (const float*)d_in[1];
    float* out = (float*)d_out;
    kernInit<<<1, 128>>>();
    kernValidCand<<<dim3(16, 16, 128), dim3(32, 32)>>>(pred, tgt);
    kernSort<<<128, 1024>>>();
    kernFallback<<<128, 256>>>(pred, tgt);
    kernHaus<<<dim3(64, 2), 1024>>>();
    kernFinal<<<1, 64>>>(out);
}